// round 8
// baseline (speedup 1.0000x reference)
#include <cuda_runtime.h>
#include <cuda_fp16.h>

#define NCODES 4096
#define DIM 64
#define NPTS 65536
#define NTIL 32
#define TILE_B 16640        // 128 codes x 64 k x fp16 + 256B csq-h2
#define MARGIN 2.0f
#define DECAY_F 0.99f
#define OMD_F 0.01f
#define EPS_F 1e-5f

__device__ float g_counts[NCODES];
__device__ float g_embed[NCODES * DIM];
__device__ float g_ncs[NCODES];
__device__ float g_factor[NCODES];
__device__ float g_csq[NCODES];
__device__ __align__(16) unsigned char g_cbB[NTIL * TILE_B];

#define OFF_B    0             // 2 x 16640 = 33280
#define OFF_TM   33280         // [pt128][t 32 pad->33][c4] fp16 = 33792 B
#define OFF_PMIN 67072         // 128 f32
#define SMEM_TOTAL 67584

static __device__ __forceinline__ unsigned hmin2u(unsigned a, unsigned b) {
    __half2 r = __hmin2(*(__half2*)&a, *(__half2*)&b);
    return *(unsigned*)&r;
}
static __device__ __forceinline__ unsigned hadd2u(unsigned a, unsigned b) {
    __half2 r = __hadd2(*(__half2*)&a, *(__half2*)&b);
    return *(unsigned*)&r;
}
static __device__ __forceinline__ unsigned packh2(float lo, float hi) {
    __half2 h = __floats2half2_rn(lo, hi);
    return *(unsigned*)&h;
}
static __device__ __forceinline__ float h2lo(unsigned u) { return __low2float(*(__half2*)&u); }
static __device__ __forceinline__ float h2hi(unsigned u) { return __high2float(*(__half2*)&u); }

static __device__ __forceinline__ void mmaA(unsigned& d0, unsigned& d1,
                                            const unsigned* a, unsigned b0, unsigned b1) {
    asm("mma.sync.aligned.m16n8k16.row.col.f16.f16.f16.f16 "
        "{%0,%1}, {%2,%3,%4,%5}, {%6,%7}, {%0,%1};"
        : "+r"(d0), "+r"(d1)
        : "r"(a[0]), "r"(a[1]), "r"(a[2]), "r"(a[3]), "r"(b0), "r"(b1));
}
static __device__ __forceinline__ void mmaZ(unsigned& d0, unsigned& d1,
                                            const unsigned* a, unsigned b0, unsigned b1) {
    asm("mma.sync.aligned.m16n8k16.row.col.f16.f16.f16.f16 "
        "{%0,%1}, {%2,%3,%4,%5}, {%6,%7}, {%8,%8};"
        : "=r"(d0), "=r"(d1)
        : "r"(a[0]), "r"(a[1]), "r"(a[2]), "r"(a[3]), "r"(b0), "r"(b1), "r"(0u));
}
static __device__ __forceinline__ void cp16(unsigned dst, const void* src) {
    asm volatile("cp.async.cg.shared.global [%0], [%1], 16;" :: "r"(dst), "l"(src));
}
#define CP_COMMIT() asm volatile("cp.async.commit_group;" ::: "memory")
#define CP_WAIT1()  asm volatile("cp.async.wait_group 1;" ::: "memory")

// B-fragment offset (layout validated R4/R6/R7), ks 0..3
static __device__ __forceinline__ unsigned bfrag_off(int tile, int n, int ks, int c) {
    int nt = n >> 3, nn = n & 7;
    return (unsigned)tile * TILE_B +
           (((ks * 8 + (nt >> 1)) * 32 + (nn * 4 + ((c & 7) >> 1))) * 16) +
           (nt & 1) * 8 + (c >> 3) * 4 + (c & 1) * 2;
}

// ---- prep ----
__global__ void prep_kernel(const float* __restrict__ codebook) {
    int i = blockIdx.x * blockDim.x + threadIdx.x;
    if (i >= NCODES * DIM) return;
    int k = i >> 6, d = i & 63;
    int tile = k >> 7, n = k & 127;
    *(__half*)(g_cbB + bfrag_off(tile, n, d >> 4, d & 15)) =
        __float2half_rn(-2.0f * codebook[i]);
    g_embed[i] = 0.0f;
    if (d == 0) {
        const float* row = codebook + (size_t)k * DIM;
        float s = 0.0f;
#pragma unroll
        for (int j = 0; j < DIM; j++) s += row[j] * row[j];
        g_csq[k] = s;
        g_counts[k] = 0.0f;
        int nt = n >> 3, c4 = (n & 7) >> 1, half = n & 1;
        *(__half*)(g_cbB + (unsigned)tile * TILE_B + 16384 +
                   ((nt * 4 + c4) * 4) + half * 2) = __float2half_rn(s);
    }
}

// ---- main: 4 warps, m32n128 per warp, 128 pts/CTA, 3 CTAs/SM ----
__global__ void __launch_bounds__(128, 3) vq_kernel(
    const float* __restrict__ x, const float* __restrict__ codebook,
    float* __restrict__ o_quant, float* __restrict__ o_idx) {
    extern __shared__ char smem[];
    const int tid = threadIdx.x, lane = tid & 31, w = tid >> 5;
    const int r0 = lane >> 2, c4 = lane & 3;

    // A fragments: 2 m-tiles (rows w*32 + mt*16 + r0, +8)
    unsigned afr[2][4][4];
#pragma unroll
    for (int mt = 0; mt < 2; mt++) {
        const float* xr0 = x + ((size_t)blockIdx.x * 128 + w * 32 + mt * 16 + r0) * DIM;
        const float* xr1 = xr0 + 8 * DIM;
#pragma unroll
        for (int ks = 0; ks < 4; ks++) {
            float2 a = *(const float2*)(xr0 + ks * 16 + 2 * c4);
            float2 b = *(const float2*)(xr1 + ks * 16 + 2 * c4);
            float2 c = *(const float2*)(xr0 + ks * 16 + 8 + 2 * c4);
            float2 d = *(const float2*)(xr1 + ks * 16 + 8 + 2 * c4);
            afr[mt][ks][0] = packh2(a.x, a.y);
            afr[mt][ks][1] = packh2(b.x, b.y);
            afr[mt][ks][2] = packh2(c.x, c.y);
            afr[mt][ks][3] = packh2(d.x, d.y);
        }
    }

    const unsigned smem_b = (unsigned)__cvta_generic_to_shared(smem + OFF_B);
#pragma unroll
    for (int t = 0; t < 2; t++) {
        const unsigned char* src = g_cbB + (size_t)t * TILE_B;
        for (int c = tid; c < TILE_B / 16; c += 128)
            cp16(smem_b + t * TILE_B + c * 16, src + c * 16);
        CP_COMMIT();
    }

    unsigned gmin[4] = {0x7BFF7BFFu, 0x7BFF7BFFu, 0x7BFF7BFFu, 0x7BFF7BFFu};
    __half* tmh = (__half*)(smem + OFF_TM);

    for (int t = 0; t < NTIL; ++t) {
        const int buf = t & 1;
        CP_WAIT1();
        __syncthreads();

        const uint4* B4 = (const uint4*)(smem + OFF_B + buf * TILE_B);
        const unsigned* csq2 = (const unsigned*)(smem + OFF_B + buf * TILE_B + 16384);

        unsigned acc[2][32];
#pragma unroll
        for (int ks = 0; ks < 4; ks++)
#pragma unroll
            for (int p = 0; p < 8; p++) {
                uint4 b = B4[(ks * 8 + p) * 32 + lane];
                if (ks == 0) {
#pragma unroll
                    for (int mt = 0; mt < 2; mt++) {
                        mmaZ(acc[mt][(p * 2 + 0) * 2], acc[mt][(p * 2 + 0) * 2 + 1],
                             afr[mt][0], b.x, b.y);
                        mmaZ(acc[mt][(p * 2 + 1) * 2], acc[mt][(p * 2 + 1) * 2 + 1],
                             afr[mt][0], b.z, b.w);
                    }
                } else {
#pragma unroll
                    for (int mt = 0; mt < 2; mt++) {
                        mmaA(acc[mt][(p * 2 + 0) * 2], acc[mt][(p * 2 + 0) * 2 + 1],
                             afr[mt][ks], b.x, b.y);
                        mmaA(acc[mt][(p * 2 + 1) * 2], acc[mt][(p * 2 + 1) * 2 + 1],
                             afr[mt][ks], b.z, b.w);
                    }
                }
            }

        unsigned cq[16];
#pragma unroll
        for (int nt = 0; nt < 16; nt++) cq[nt] = csq2[nt * 4 + c4];

#pragma unroll
        for (int mt = 0; mt < 2; mt++) {
#pragma unroll
            for (int slot = 0; slot < 2; slot++) {
                unsigned m[8];
#pragma unroll
                for (int j = 0; j < 8; j++)
                    m[j] = hmin2u(hadd2u(acc[mt][(j + 0) * 2 + slot], cq[j]),
                                  hadd2u(acc[mt][(j + 8) * 2 + slot], cq[j + 8]));
#pragma unroll
                for (int j = 0; j < 4; j++) m[j] = hmin2u(m[j], m[j + 4]);
                unsigned tv = hmin2u(hmin2u(m[0], m[1]), hmin2u(m[2], m[3]));
                gmin[mt * 2 + slot] = hmin2u(gmin[mt * 2 + slot], tv);
                const int pt = w * 32 + mt * 16 + slot * 8 + r0;
                tmh[(pt * 33 + t) * 4 + c4] =
                    __hmin(*(__half*)&tv, *((__half*)&tv + 1));
            }
        }

        __syncthreads();
        if (t + 2 < NTIL) {
            const unsigned char* src = g_cbB + (size_t)(t + 2) * TILE_B;
            for (int c = tid; c < TILE_B / 16; c += 128)
                cp16(smem_b + buf * TILE_B + c * 16, src + c * 16);
        }
        CP_COMMIT();
    }

    // noisy per-point min
    float* pminS = (float*)(smem + OFF_PMIN);
#pragma unroll
    for (int s = 0; s < 4; s++) {
        unsigned g = gmin[s];
        g = hmin2u(g, __shfl_xor_sync(0xffffffffu, g, 1));
        g = hmin2u(g, __shfl_xor_sync(0xffffffffu, g, 2));
        if (c4 == 0)
            pminS[w * 32 + (s >> 1) * 16 + (s & 1) * 8 + r0] = fminf(h2lo(g), h2hi(g));
    }
    __syncwarp();

    // recovery + exact refine: warp per point, 1 lane = 1 code per hit subset
    const uint2* tmv = (const uint2*)(smem + OFF_TM);
    for (int ii = 0; ii < 32; ii++) {
        const int pl = w * 32 + ii;
        const int gpt = blockIdx.x * 128 + pl;
        const float th = pminS[pl] + MARGIN;

        // x row in regs (broadcast loads), exact xsq
        float4 xv[16];
        const float4* xr = (const float4*)(x + (size_t)gpt * DIM);
#pragma unroll
        for (int j = 0; j < 16; j++) xv[j] = xr[j];
        float xsq = 0.0f;
#pragma unroll
        for (int j = 0; j < 16; j++) {
            xsq = fmaf(xv[j].x, xv[j].x, xsq);
            xsq = fmaf(xv[j].y, xv[j].y, xsq);
            xsq = fmaf(xv[j].z, xv[j].z, xsq);
            xsq = fmaf(xv[j].w, xv[j].w, xsq);
        }

        uint2 e = tmv[pl * 33 + lane];  // tile = lane; 4 fp16 subset-mins (c4 0..3)
        unsigned m4 = 0;
        if (h2lo(e.x) < th) m4 |= 1u;
        if (h2hi(e.x) < th) m4 |= 2u;
        if (h2lo(e.y) < th) m4 |= 4u;
        if (h2hi(e.y) < th) m4 |= 8u;

        float bd = 3.4e38f;
        int bi = 0x7FFFFFFF;
        unsigned hitb = __ballot_sync(0xffffffffu, m4 != 0);
        while (hitb) {
            const int src = __ffs(hitb) - 1;
            hitb &= hitb - 1;
            unsigned m = __shfl_sync(0xffffffffu, m4, src);
#pragma unroll 1
            for (int cb = 0; cb < 4; cb++) {
                if (!(m & (1u << cb))) continue;
                // subset codes: src*128 + nt*8 + 2*cb + h; lane = nt*2+h
                const int code = src * 128 + (lane >> 1) * 8 + 2 * cb + (lane & 1);
                const float4* cr = (const float4*)(codebook + (size_t)code * DIM);
                float dot = 0.0f;
#pragma unroll
                for (int j = 0; j < 16; j++) {
                    float4 ca = cr[j];
                    dot = fmaf(xv[j].x, ca.x, dot);
                    dot = fmaf(xv[j].y, ca.y, dot);
                    dot = fmaf(xv[j].z, ca.z, dot);
                    dot = fmaf(xv[j].w, ca.w, dot);
                }
                float dd = fmaf(-2.0f, dot, xsq) + g_csq[code];
                int wi = code;
#pragma unroll
                for (int o = 1; o <= 16; o <<= 1) {
                    float od = __shfl_xor_sync(0xffffffffu, dd, o);
                    int oi = __shfl_xor_sync(0xffffffffu, wi, o);
                    if (od < dd || (od == dd && oi < wi)) { dd = od; wi = oi; }
                }
                if (dd < bd || (dd == bd && wi < bi)) { bd = dd; bi = wi; }
            }
        }

        if (lane == 0) o_idx[gpt] = (float)bi;
        ((float2*)(o_quant + (size_t)gpt * DIM))[lane] =
            ((const float2*)(codebook + (size_t)bi * DIM))[lane];
        float2 xe = ((const float2*)(x + (size_t)gpt * DIM))[lane];
        if (lane == 0) atomicAdd(&g_counts[bi], 1.0f);
        atomicAdd(&g_embed[(size_t)bi * DIM + 2 * lane], xe.x);
        atomicAdd(&g_embed[(size_t)bi * DIM + 2 * lane + 1], xe.y);
    }
}

__global__ void finalize1_kernel(const float* __restrict__ cluster_size,
                                 float* __restrict__ o_cs) {
    __shared__ float warpsum[32];
    __shared__ float s_n;
    float local = 0.0f;
    for (int k = threadIdx.x; k < NCODES; k += blockDim.x) {
        float ncs = DECAY_F * cluster_size[k] + OMD_F * g_counts[k];
        o_cs[k] = ncs;
        g_ncs[k] = ncs;
        local += ncs;
    }
#pragma unroll
    for (int o = 16; o; o >>= 1) local += __shfl_down_sync(0xffffffffu, local, o);
    if ((threadIdx.x & 31) == 0) warpsum[threadIdx.x >> 5] = local;
    __syncthreads();
    if (threadIdx.x < 32) {
        float v = (threadIdx.x < (blockDim.x >> 5)) ? warpsum[threadIdx.x] : 0.0f;
#pragma unroll
        for (int o = 16; o; o >>= 1) v += __shfl_down_sync(0xffffffffu, v, o);
        if (threadIdx.x == 0) s_n = v;
    }
    __syncthreads();
    float n = s_n;
    float denom = n + (float)NCODES * EPS_F;
    for (int k = threadIdx.x; k < NCODES; k += blockDim.x) {
        float sm = (g_ncs[k] + EPS_F) / denom * n;
        g_factor[k] = 1.0f / sm;
    }
}

__global__ void finalize2_kernel(const float* __restrict__ ema_w,
                                 float* __restrict__ o_cb,
                                 float* __restrict__ o_ema) {
    int i = blockIdx.x * blockDim.x + threadIdx.x;
    if (i >= NCODES * DIM) return;
    float e = DECAY_F * ema_w[i] + OMD_F * g_embed[i];
    o_ema[i] = e;
    o_cb[i] = e * g_factor[i >> 6];
}

extern "C" void kernel_launch(void* const* d_in, const int* in_sizes, int n_in,
                              void* d_out, int out_size) {
    const float* x            = (const float*)d_in[0];
    const float* codebook     = (const float*)d_in[1];
    const float* cluster_size = (const float*)d_in[2];
    const float* ema_w        = (const float*)d_in[3];

    float* out     = (float*)d_out;
    float* o_quant = out;
    float* o_idx   = o_quant + (size_t)NPTS * DIM;
    float* o_cb    = o_idx + NPTS;
    float* o_cs    = o_cb + (size_t)NCODES * DIM;
    float* o_ema   = o_cs + NCODES;

    static int smem_set = 0;
    if (!smem_set) {
        cudaFuncSetAttribute(vq_kernel, cudaFuncAttributeMaxDynamicSharedMemorySize, SMEM_TOTAL);
        smem_set = 1;
    }

    prep_kernel<<<(NCODES * DIM + 255) / 256, 256>>>(codebook);
    vq_kernel<<<NPTS / 128, 128, SMEM_TOTAL>>>(x, codebook, o_quant, o_idx);
    finalize1_kernel<<<1, 1024>>>(cluster_size, o_cs);
    finalize2_kernel<<<(NCODES * DIM + 255) / 256, 256>>>(ema_w, o_cb, o_ema);
}

// round 9
// speedup vs baseline: 1.4978x; 1.4978x over previous
#include <cuda_runtime.h>
#include <cuda_fp16.h>

#define NCODES 4096
#define DIM 64
#define NPTS 65536
#define NTIL 32
#define TILE_B 16640        // 128 codes x 64 k x fp16 + 256B csq-h2
#define MARGIN 1.25f
#define DECAY_F 0.99f
#define OMD_F 0.01f
#define EPS_F 1e-5f

__device__ float g_counts[NCODES];
__device__ float g_embed[NCODES * DIM];
__device__ float g_ncs[NCODES];
__device__ float g_factor[NCODES];
__device__ float g_csq[NCODES];
__device__ __align__(16) unsigned char g_cbB[NTIL * TILE_B];

#define OFF_B    0             // 2 x 16640 = 33280
#define OFF_TM   33280         // [pt128][t 32 pad->33][c4] u32 = 67584
#define OFF_PMIN 100864        // 128 f32
#define SMEM_TOTAL 101376

static __device__ __forceinline__ unsigned hmin2u(unsigned a, unsigned b) {
    __half2 r = __hmin2(*(__half2*)&a, *(__half2*)&b);
    return *(unsigned*)&r;
}
static __device__ __forceinline__ unsigned hadd2u(unsigned a, unsigned b) {
    __half2 r = __hadd2(*(__half2*)&a, *(__half2*)&b);
    return *(unsigned*)&r;
}
static __device__ __forceinline__ unsigned packh2(float lo, float hi) {
    __half2 h = __floats2half2_rn(lo, hi);
    return *(unsigned*)&h;
}
static __device__ __forceinline__ float h2lo(unsigned u) { return __low2float(*(__half2*)&u); }
static __device__ __forceinline__ float h2hi(unsigned u) { return __high2float(*(__half2*)&u); }

static __device__ __forceinline__ void mmaA(unsigned& d0, unsigned& d1,
                                            const unsigned* a, unsigned b0, unsigned b1) {
    asm("mma.sync.aligned.m16n8k16.row.col.f16.f16.f16.f16 "
        "{%0,%1}, {%2,%3,%4,%5}, {%6,%7}, {%0,%1};"
        : "+r"(d0), "+r"(d1)
        : "r"(a[0]), "r"(a[1]), "r"(a[2]), "r"(a[3]), "r"(b0), "r"(b1));
}
static __device__ __forceinline__ void mmaZ(unsigned& d0, unsigned& d1,
                                            const unsigned* a, unsigned b0, unsigned b1) {
    asm("mma.sync.aligned.m16n8k16.row.col.f16.f16.f16.f16 "
        "{%0,%1}, {%2,%3,%4,%5}, {%6,%7}, {%8,%8};"
        : "=r"(d0), "=r"(d1)
        : "r"(a[0]), "r"(a[1]), "r"(a[2]), "r"(a[3]), "r"(b0), "r"(b1), "r"(0u));
}
static __device__ __forceinline__ void cp16(unsigned dst, const void* src) {
    asm volatile("cp.async.cg.shared.global [%0], [%1], 16;" :: "r"(dst), "l"(src));
}
#define CP_COMMIT() asm volatile("cp.async.commit_group;" ::: "memory")
#define CP_WAIT1()  asm volatile("cp.async.wait_group 1;" ::: "memory")

// B-fragment offset (layout validated R4/R6/R7), ks 0..3
static __device__ __forceinline__ unsigned bfrag_off(int tile, int n, int ks, int c) {
    int nt = n >> 3, nn = n & 7;
    return (unsigned)tile * TILE_B +
           (((ks * 8 + (nt >> 1)) * 32 + (nn * 4 + ((c & 7) >> 1))) * 16) +
           (nt & 1) * 8 + (c >> 3) * 4 + (c & 1) * 2;
}

// ---- prep: B frags fp16(-2c); csq-h2 blob per tile; csq f32; zero scratch ----
__global__ void prep_kernel(const float* __restrict__ codebook) {
    int i = blockIdx.x * blockDim.x + threadIdx.x;
    if (i >= NCODES * DIM) return;
    int k = i >> 6, d = i & 63;
    int tile = k >> 7, n = k & 127;
    *(__half*)(g_cbB + bfrag_off(tile, n, d >> 4, d & 15)) =
        __float2half_rn(-2.0f * codebook[i]);
    g_embed[i] = 0.0f;
    if (d == 0) {
        const float* row = codebook + (size_t)k * DIM;
        float s = 0.0f;
#pragma unroll
        for (int j = 0; j < DIM; j++) s += row[j] * row[j];
        g_csq[k] = s;
        g_counts[k] = 0.0f;
        int nt = n >> 3, c4 = (n & 7) >> 1, half = n & 1;
        *(__half*)(g_cbB + (unsigned)tile * TILE_B + 16384 +
                   ((nt * 4 + c4) * 4) + half * 2) = __float2half_rn(s);
    }
}

// ---- main: 4 warps, m32n128 per warp, 128 pts/CTA, 2 CTAs/SM ----
__global__ void __launch_bounds__(128, 2) vq_kernel(
    const float* __restrict__ x, const float* __restrict__ codebook,
    float* __restrict__ o_quant, float* __restrict__ o_idx) {
    extern __shared__ char smem[];
    const int tid = threadIdx.x, lane = tid & 31, w = tid >> 5;
    const int r0 = lane >> 2, c4 = lane & 3;

    // A fragments: 2 m-tiles (rows w*32 + mt*16 + r0, +8)
    unsigned afr[2][4][4];
#pragma unroll
    for (int mt = 0; mt < 2; mt++) {
        const float* xr0 = x + ((size_t)blockIdx.x * 128 + w * 32 + mt * 16 + r0) * DIM;
        const float* xr1 = xr0 + 8 * DIM;
#pragma unroll
        for (int ks = 0; ks < 4; ks++) {
            float2 a = *(const float2*)(xr0 + ks * 16 + 2 * c4);
            float2 b = *(const float2*)(xr1 + ks * 16 + 2 * c4);
            float2 c = *(const float2*)(xr0 + ks * 16 + 8 + 2 * c4);
            float2 d = *(const float2*)(xr1 + ks * 16 + 8 + 2 * c4);
            afr[mt][ks][0] = packh2(a.x, a.y);
            afr[mt][ks][1] = packh2(b.x, b.y);
            afr[mt][ks][2] = packh2(c.x, c.y);
            afr[mt][ks][3] = packh2(d.x, d.y);
        }
    }

    const unsigned smem_b = (unsigned)__cvta_generic_to_shared(smem + OFF_B);
#pragma unroll
    for (int t = 0; t < 2; t++) {
        const unsigned char* src = g_cbB + (size_t)t * TILE_B;
        for (int c = tid; c < TILE_B / 16; c += 128)
            cp16(smem_b + t * TILE_B + c * 16, src + c * 16);
        CP_COMMIT();
    }

    unsigned gmin[4] = {0x7BFF7BFFu, 0x7BFF7BFFu, 0x7BFF7BFFu, 0x7BFF7BFFu};
    unsigned* tm = (unsigned*)(smem + OFF_TM);

    for (int t = 0; t < NTIL; ++t) {
        const int buf = t & 1;
        CP_WAIT1();
        __syncthreads();

        const uint4* B4 = (const uint4*)(smem + OFF_B + buf * TILE_B);
        const unsigned* csq2 = (const unsigned*)(smem + OFF_B + buf * TILE_B + 16384);

        unsigned acc[2][32];
#pragma unroll
        for (int ks = 0; ks < 4; ks++)
#pragma unroll
            for (int p = 0; p < 8; p++) {
                uint4 b = B4[(ks * 8 + p) * 32 + lane];
                if (ks == 0) {
#pragma unroll
                    for (int mt = 0; mt < 2; mt++) {
                        mmaZ(acc[mt][(p * 2 + 0) * 2], acc[mt][(p * 2 + 0) * 2 + 1],
                             afr[mt][0], b.x, b.y);
                        mmaZ(acc[mt][(p * 2 + 1) * 2], acc[mt][(p * 2 + 1) * 2 + 1],
                             afr[mt][0], b.z, b.w);
                    }
                } else {
#pragma unroll
                    for (int mt = 0; mt < 2; mt++) {
                        mmaA(acc[mt][(p * 2 + 0) * 2], acc[mt][(p * 2 + 0) * 2 + 1],
                             afr[mt][ks], b.x, b.y);
                        mmaA(acc[mt][(p * 2 + 1) * 2], acc[mt][(p * 2 + 1) * 2 + 1],
                             afr[mt][ks], b.z, b.w);
                    }
                }
            }

        // epilogue: add csq (h2), hmin trees, store subset mins
        unsigned cq[16];
#pragma unroll
        for (int nt = 0; nt < 16; nt++) cq[nt] = csq2[nt * 4 + c4];

#pragma unroll
        for (int mt = 0; mt < 2; mt++) {
#pragma unroll
            for (int slot = 0; slot < 2; slot++) {
                unsigned m[8];
#pragma unroll
                for (int j = 0; j < 8; j++)
                    m[j] = hmin2u(hadd2u(acc[mt][(j + 0) * 2 + slot], cq[j]),
                                  hadd2u(acc[mt][(j + 8) * 2 + slot], cq[j + 8]));
#pragma unroll
                for (int j = 0; j < 4; j++) m[j] = hmin2u(m[j], m[j + 4]);
                unsigned tv = hmin2u(hmin2u(m[0], m[1]), hmin2u(m[2], m[3]));
                gmin[mt * 2 + slot] = hmin2u(gmin[mt * 2 + slot], tv);
                const int pt = w * 32 + mt * 16 + slot * 8 + r0;
                tm[(pt * 33 + t) * 4 + c4] = tv;
            }
        }

        __syncthreads();
        if (t + 2 < NTIL) {
            const unsigned char* src = g_cbB + (size_t)(t + 2) * TILE_B;
            for (int c = tid; c < TILE_B / 16; c += 128)
                cp16(smem_b + buf * TILE_B + c * 16, src + c * 16);
        }
        CP_COMMIT();
    }

    // noisy per-point min
    float* pminS = (float*)(smem + OFF_PMIN);
#pragma unroll
    for (int s = 0; s < 4; s++) {
        unsigned g = gmin[s];
        g = hmin2u(g, __shfl_xor_sync(0xffffffffu, g, 1));
        g = hmin2u(g, __shfl_xor_sync(0xffffffffu, g, 2));
        if (c4 == 0)
            pminS[w * 32 + (s >> 1) * 16 + (s & 1) * 8 + r0] = fminf(h2lo(g), h2hi(g));
    }
    __syncwarp();

    // recovery + exact refine, warp per point (32 points per warp)
    const uint4* tm4 = (const uint4*)tm;
    for (int ii = 0; ii < 32; ii++) {
        const int pl = w * 32 + ii;
        const int gpt = blockIdx.x * 128 + pl;
        const float th = pminS[pl] + MARGIN;

        float2 xv2 = ((const float2*)(x + (size_t)gpt * DIM))[lane];
        float xsq = fmaf(xv2.x, xv2.x, xv2.y * xv2.y);
#pragma unroll
        for (int o = 1; o <= 16; o <<= 1) xsq += __shfl_xor_sync(0xffffffffu, xsq, o);

        uint4 e = tm4[pl * 33 + lane];  // tile = lane, components = c4 0..3
        unsigned m8 = 0;
        if (h2lo(e.x) < th) m8 |= 1u;
        if (h2hi(e.x) < th) m8 |= 2u;
        if (h2lo(e.y) < th) m8 |= 4u;
        if (h2hi(e.y) < th) m8 |= 8u;
        if (h2lo(e.z) < th) m8 |= 16u;
        if (h2hi(e.z) < th) m8 |= 32u;
        if (h2lo(e.w) < th) m8 |= 64u;
        if (h2hi(e.w) < th) m8 |= 128u;

        float bd = 3.4e38f;
        int bi = 0x7FFFFFFF;
        unsigned hitb = __ballot_sync(0xffffffffu, m8 != 0);
        while (hitb) {
            const int src = __ffs(hitb) - 1;
            hitb &= hitb - 1;
            unsigned m = __shfl_sync(0xffffffffu, m8, src);
            for (int bit = 0; bit < 8; bit++) {
                if (!(m & (1u << bit))) continue;
                const int code = src * 128 + (lane >> 1) * 8 + (bit >> 1) * 2 + (bit & 1);
                const int part = lane & 1;
                const float4* xr = (const float4*)(x + (size_t)gpt * DIM) + part * 8;
                const float4* cr = (const float4*)(codebook + (size_t)code * DIM) + part * 8;
                float dot = 0.0f;
#pragma unroll
                for (int j = 0; j < 8; j++) {
                    float4 xa = xr[j], ca = cr[j];
                    dot = fmaf(xa.x, ca.x, dot);
                    dot = fmaf(xa.y, ca.y, dot);
                    dot = fmaf(xa.z, ca.z, dot);
                    dot = fmaf(xa.w, ca.w, dot);
                }
                dot += __shfl_xor_sync(0xffffffffu, dot, 1);
                float dd = fmaf(-2.0f, dot, xsq) + g_csq[code];
                int wi = code;
#pragma unroll
                for (int o = 2; o <= 16; o <<= 1) {
                    float od = __shfl_xor_sync(0xffffffffu, dd, o);
                    int oi = __shfl_xor_sync(0xffffffffu, wi, o);
                    if (od < dd || (od == dd && oi < wi)) { dd = od; wi = oi; }
                }
                if (dd < bd || (dd == bd && wi < bi)) { bd = dd; bi = wi; }
            }
        }

        if (lane == 0) o_idx[gpt] = (float)bi;
        ((float2*)(o_quant + (size_t)gpt * DIM))[lane] =
            ((const float2*)(codebook + (size_t)bi * DIM))[lane];
        if (lane == 0) atomicAdd(&g_counts[bi], 1.0f);
        atomicAdd(&g_embed[(size_t)bi * DIM + 2 * lane], xv2.x);
        atomicAdd(&g_embed[(size_t)bi * DIM + 2 * lane + 1], xv2.y);
    }
}

__global__ void finalize1_kernel(const float* __restrict__ cluster_size,
                                 float* __restrict__ o_cs) {
    __shared__ float warpsum[32];
    __shared__ float s_n;
    float local = 0.0f;
    for (int k = threadIdx.x; k < NCODES; k += blockDim.x) {
        float ncs = DECAY_F * cluster_size[k] + OMD_F * g_counts[k];
        o_cs[k] = ncs;
        g_ncs[k] = ncs;
        local += ncs;
    }
#pragma unroll
    for (int o = 16; o; o >>= 1) local += __shfl_down_sync(0xffffffffu, local, o);
    if ((threadIdx.x & 31) == 0) warpsum[threadIdx.x >> 5] = local;
    __syncthreads();
    if (threadIdx.x < 32) {
        float v = (threadIdx.x < (blockDim.x >> 5)) ? warpsum[threadIdx.x] : 0.0f;
#pragma unroll
        for (int o = 16; o; o >>= 1) v += __shfl_down_sync(0xffffffffu, v, o);
        if (threadIdx.x == 0) s_n = v;
    }
    __syncthreads();
    float n = s_n;
    float denom = n + (float)NCODES * EPS_F;
    for (int k = threadIdx.x; k < NCODES; k += blockDim.x) {
        float sm = (g_ncs[k] + EPS_F) / denom * n;
        g_factor[k] = 1.0f / sm;
    }
}

__global__ void finalize2_kernel(const float* __restrict__ ema_w,
                                 float* __restrict__ o_cb,
                                 float* __restrict__ o_ema) {
    int i = blockIdx.x * blockDim.x + threadIdx.x;
    if (i >= NCODES * DIM) return;
    float e = DECAY_F * ema_w[i] + OMD_F * g_embed[i];
    o_ema[i] = e;
    o_cb[i] = e * g_factor[i >> 6];
}

extern "C" void kernel_launch(void* const* d_in, const int* in_sizes, int n_in,
                              void* d_out, int out_size) {
    const float* x            = (const float*)d_in[0];
    const float* codebook     = (const float*)d_in[1];
    const float* cluster_size = (const float*)d_in[2];
    const float* ema_w        = (const float*)d_in[3];

    float* out     = (float*)d_out;
    float* o_quant = out;
    float* o_idx   = o_quant + (size_t)NPTS * DIM;
    float* o_cb    = o_idx + NPTS;
    float* o_cs    = o_cb + (size_t)NCODES * DIM;
    float* o_ema   = o_cs + NCODES;

    static int smem_set = 0;
    if (!smem_set) {
        cudaFuncSetAttribute(vq_kernel, cudaFuncAttributeMaxDynamicSharedMemorySize, SMEM_TOTAL);
        smem_set = 1;
    }

    prep_kernel<<<(NCODES * DIM + 255) / 256, 256>>>(codebook);
    vq_kernel<<<NPTS / 128, 128, SMEM_TOTAL>>>(x, codebook, o_quant, o_idx);
    finalize1_kernel<<<1, 1024>>>(cluster_size, o_cs);
    finalize2_kernel<<<(NCODES * DIM + 255) / 256, 256>>>(ema_w, o_cb, o_ema);
}